// round 1
// baseline (speedup 1.0000x reference)
#include <cuda_runtime.h>
#include <cstdint>

#define NN    2000
#define D     16
#define ROWS  512            // B*T = 8*64
#define TILE  (ROWS*D)       // 8192 floats = 32KB
#define BR    3

// Scratch (device globals: no allocation allowed in kernel_launch)
__device__ float g_h1[600  * TILE];   // level-1 hidden states
__device__ float g_h2[1800 * TILE];   // level-2 hidden states
__device__ int   g_counts[NN];

__device__ __forceinline__ void red_add_v4(float* p, float a, float b, float c, float d) {
    asm volatile("red.global.add.v4.f32 [%0], {%1,%2,%3,%4};"
                 :: "l"(p), "f"(a), "f"(b), "f"(c), "f"(d) : "memory");
}

__global__ void zero_counts_kernel() {
    int i = blockIdx.x * blockDim.x + threadIdx.x;
    if (i < NN) g_counts[i] = 0;
}

__global__ void count_kernel(const int* __restrict__ cn3, int n) {
    int i = blockIdx.x * blockDim.x + threadIdx.x;
    if (i < n) atomicAdd(&g_counts[cn3[i]], 1);
}

// out[n] = 0 for nodes with leaves (accumulated later), x[n] otherwise
__global__ void init_out_kernel(float* __restrict__ out, const float* __restrict__ x, int total4) {
    int i = blockIdx.x * blockDim.x + threadIdx.x;
    if (i >= total4) return;
    int node = i >> 11;                 // TILE/4 = 2048 float4 per node
    float4 v = make_float4(0.f, 0.f, 0.f, 0.f);
    if (g_counts[node] == 0) v = ((const float4*)x)[i];
    ((float4*)out)[i] = v;
}

// One block per parent entry; computes fc(parent) once, emits its BR children.
// MODE 0: parent = x[root_ids[pe]],  store into g_h1
// MODE 1: parent = g_h1[pe],         store into g_h2
// MODE 2: parent = g_h2[pe],         scale by 1/count, red.v4 into d_out
template<int MODE>
__global__ void __launch_bounds__(512) level_kernel(
    const float* __restrict__ x, const float* __restrict__ A,
    const float* __restrict__ W, const float* __restrict__ bias,
    const int* __restrict__ root_ids,
    const int* __restrict__ pe, const int* __restrict__ pn, const int* __restrict__ cn,
    float* __restrict__ out)
{
    __shared__ float sW[D*D];
    __shared__ float sb[D];
    __shared__ float sScale[BR][D];
    __shared__ int   sCn[BR];
    __shared__ float sInv[BR];

    const int p = blockIdx.x;
    const int t = threadIdx.x;

    if (t < D*D) sW[t] = W[t];
    if (t < D)   sb[t] = bias[t];
    if (t < BR*D) {
        int c = t >> 4, f = t & 15;
        int j = p * BR + c;
        int pnj = pn[j], cnj = cn[j];
        // scale[j][f] = A[f, pn[j], cn[j]]
        sScale[c][f] = A[(size_t)f * NN * NN + (size_t)pnj * NN + (size_t)cnj];
        if (f == 0) {
            sCn[c] = cnj;
            if (MODE == 2) sInv[c] = 1.0f / (float)g_counts[cnj];
        }
    }

    // parent tile (all BR children of this block share it; pe[p*BR..] are equal)
    const float* ptile;
    {
        int pidx = pe[p * BR];
        if (MODE == 0)      ptile = x    + (size_t)root_ids[pidx] * TILE;
        else if (MODE == 1) ptile = g_h1 + (size_t)pidx * TILE;
        else                ptile = g_h2 + (size_t)pidx * TILE;
    }

    // each thread owns one (b,t) row of 16 floats: 64B coalesced float4 loads
    const float4* pr = (const float4*)(ptile + (size_t)t * D);
    float4 a0 = pr[0], a1 = pr[1], a2 = pr[2], a3 = pr[3];
    float h[16] = {a0.x,a0.y,a0.z,a0.w, a1.x,a1.y,a1.z,a1.w,
                   a2.x,a2.y,a2.z,a2.w, a3.x,a3.y,a3.z,a3.w};
    __syncthreads();

    // fc: y[f] = b[f] + sum_d h[d] * W[f,d]   (W row-major [f*16+d], shared broadcast)
    float y[16];
    #pragma unroll
    for (int f = 0; f < 16; f++) y[f] = sb[f];
    #pragma unroll
    for (int d = 0; d < 16; d++) {
        float hd = h[d];
        #pragma unroll
        for (int f = 0; f < 16; f++) y[f] = fmaf(hd, sW[f*16 + d], y[f]);
    }

    #pragma unroll
    for (int c = 0; c < BR; c++) {
        int cnj = sCn[c];
        const float4* xr = (const float4*)(x + (size_t)cnj * TILE + (size_t)t * D);
        float4 x0 = xr[0], x1 = xr[1], x2 = xr[2], x3 = xr[3];
        float xv[16] = {x0.x,x0.y,x0.z,x0.w, x1.x,x1.y,x1.z,x1.w,
                        x2.x,x2.y,x2.z,x2.w, x3.x,x3.y,x3.z,x3.w};
        float o[16];
        #pragma unroll
        for (int f = 0; f < 16; f++) o[f] = fmaf(y[f], sScale[c][f], xv[f]);

        if (MODE == 2) {
            float inv = sInv[c];
            float* dst = out + (size_t)cnj * TILE + (size_t)t * D;
            red_add_v4(dst + 0,  o[0]*inv,  o[1]*inv,  o[2]*inv,  o[3]*inv);
            red_add_v4(dst + 4,  o[4]*inv,  o[5]*inv,  o[6]*inv,  o[7]*inv);
            red_add_v4(dst + 8,  o[8]*inv,  o[9]*inv,  o[10]*inv, o[11]*inv);
            red_add_v4(dst + 12, o[12]*inv, o[13]*inv, o[14]*inv, o[15]*inv);
        } else {
            float* hdst = (MODE == 0) ? g_h1 : g_h2;
            float4* dst = (float4*)(hdst + ((size_t)p * BR + c) * TILE + (size_t)t * D);
            dst[0] = make_float4(o[0],  o[1],  o[2],  o[3]);
            dst[1] = make_float4(o[4],  o[5],  o[6],  o[7]);
            dst[2] = make_float4(o[8],  o[9],  o[10], o[11]);
            dst[3] = make_float4(o[12], o[13], o[14], o[15]);
        }
    }
}

extern "C" void kernel_launch(void* const* d_in, const int* in_sizes, int n_in,
                              void* d_out, int out_size) {
    const float* x    = (const float*)d_in[0];
    const float* A    = (const float*)d_in[1];
    const float* W    = (const float*)d_in[2];
    const float* b    = (const float*)d_in[3];
    const int*   root = (const int*)d_in[4];
    const int*   pe1  = (const int*)d_in[5];
    const int*   pn1  = (const int*)d_in[6];
    const int*   cn1  = (const int*)d_in[7];
    const int*   pe2  = (const int*)d_in[8];
    const int*   pn2  = (const int*)d_in[9];
    const int*   cn2  = (const int*)d_in[10];
    const int*   pe3  = (const int*)d_in[11];
    const int*   pn3  = (const int*)d_in[12];
    const int*   cn3  = (const int*)d_in[13];
    float* out = (float*)d_out;

    const int n1 = in_sizes[5];    // 600
    const int n2 = in_sizes[8];    // 1800
    const int n3 = in_sizes[11];   // 5400

    zero_counts_kernel<<<(NN + 255) / 256, 256>>>();
    count_kernel<<<(n3 + 255) / 256, 256>>>(cn3, n3);

    const int total4 = out_size / 4;
    init_out_kernel<<<(total4 + 255) / 256, 256>>>(out, x, total4);

    level_kernel<0><<<n1 / BR, 512>>>(x, A, W, b, root, pe1, pn1, cn1, nullptr);
    level_kernel<1><<<n2 / BR, 512>>>(x, A, W, b, root, pe2, pn2, cn2, nullptr);
    level_kernel<2><<<n3 / BR, 512>>>(x, A, W, b, root, pe3, pn3, cn3, out);
}

// round 2
// speedup vs baseline: 1.2380x; 1.2380x over previous
#include <cuda_runtime.h>
#include <cstdint>

#define NN    2000
#define D     16
#define TILE  8192           // B*T*D = 8*64*16
#define BR    3
#define HALF_ROWS 256        // rows per block (tile has 512 rows)
#define MAXLEAF 8192
#define CH    8              // leaf chunk in gather

// Scratch (device globals: no allocation allowed in kernel_launch)
__device__ float g_y1[600  * TILE];   // fc(h1)
__device__ float g_y2[1800 * TILE];   // fc(h2)
__device__ int   g_counts[NN];
__device__ int   g_off[NN];
__device__ int   g_perm[MAXLEAF];

__device__ __forceinline__ void fc16(const float h[16], const float* __restrict__ sW,
                                     const float* __restrict__ sb, float y[16]) {
    #pragma unroll
    for (int f = 0; f < 16; f++) y[f] = sb[f];
    #pragma unroll
    for (int d = 0; d < 16; d++) {
        float hd = h[d];
        #pragma unroll
        for (int f = 0; f < 16; f++) y[f] = fmaf(hd, sW[f*16 + d], y[f]);
    }
}

// One block: counts, exclusive-scan offsets, scatter permutation.
__global__ void __launch_bounds__(1024) prep_kernel(const int* __restrict__ cn3, int n3) {
    __shared__ int sCnt[2048];
    __shared__ int sScan[2048];
    const int t = threadIdx.x;

    sCnt[t] = 0; sCnt[t + 1024] = 0;
    __syncthreads();
    for (int j = t; j < n3; j += 1024) atomicAdd(&sCnt[cn3[j]], 1);
    __syncthreads();

    // exclusive scan: shift then Hillis-Steele inclusive
    sScan[t]        = (t == 0) ? 0 : sCnt[t - 1];
    sScan[t + 1024] = sCnt[t + 1023];
    __syncthreads();
    for (int d = 1; d < 2048; d <<= 1) {
        int a = sScan[t]        + ((t >= d)        ? sScan[t - d]        : 0);
        int b = sScan[t + 1024] + ((t + 1024 >= d) ? sScan[t + 1024 - d] : 0);
        __syncthreads();
        sScan[t] = a; sScan[t + 1024] = b;
        __syncthreads();
    }

    if (t < NN)        { g_counts[t] = sCnt[t];               g_off[t] = sScan[t]; }
    if (t + 1024 < NN) { g_counts[t+1024] = sCnt[t+1024];     g_off[t+1024] = sScan[t+1024]; }

    // scatter: reuse sCnt as cursor
    sCnt[t] = 0; sCnt[t + 1024] = 0;
    __syncthreads();
    for (int j = t; j < n3; j += 1024) {
        int c = cn3[j];
        int pos = atomicAdd(&sCnt[c], 1);
        g_perm[sScan[c] + pos] = j;
    }
}

// MODE 0: parent = x[root_ids[pe]] (apply fc to parent); store y1 = fc(h1)
// MODE 1: parent = g_y1[pe] (already fc'd);              store y2 = fc(h2)
template<int MODE>
__global__ void __launch_bounds__(256) level_kernel(
    const float* __restrict__ x, const float* __restrict__ A,
    const float* __restrict__ W, const float* __restrict__ bias,
    const int* __restrict__ root_ids,
    const int* __restrict__ pe, const int* __restrict__ pn, const int* __restrict__ cn)
{
    __shared__ float sW[256];
    __shared__ float sb[16];
    __shared__ float sScale[BR][16];
    __shared__ int   sCn[BR];

    const int p    = blockIdx.x >> 1;
    const int half = blockIdx.x & 1;
    const int t    = threadIdx.x;
    const int r    = half * HALF_ROWS + t;

    sW[t] = W[t];
    if (t < 16) sb[t] = bias[t];
    if (t < BR * 16) {
        int c = t >> 4, f = t & 15;
        int j = p * BR + c;
        int pnj = pn[j], cnj = cn[j];
        sScale[c][f] = A[(size_t)f * NN * NN + (size_t)pnj * NN + (size_t)cnj];
        if (f == 0) sCn[c] = cnj;
    }

    const float* ptile;
    {
        int pidx = pe[p * BR];
        if (MODE == 0) ptile = x    + (size_t)root_ids[pidx] * TILE;
        else           ptile = g_y1 + (size_t)pidx * TILE;
    }
    const float4* pr = (const float4*)(ptile + (size_t)r * D);
    float4 a0 = pr[0], a1 = pr[1], a2 = pr[2], a3 = pr[3];
    float h[16] = {a0.x,a0.y,a0.z,a0.w, a1.x,a1.y,a1.z,a1.w,
                   a2.x,a2.y,a2.z,a2.w, a3.x,a3.y,a3.z,a3.w};
    __syncthreads();

    float y[16];
    if (MODE == 0) {
        fc16(h, sW, sb, y);            // y = fc(parent)
    } else {
        #pragma unroll
        for (int f = 0; f < 16; f++) y[f] = h[f];   // parent already fc'd
    }

    float* ybuf = (MODE == 0) ? g_y1 : g_y2;
    #pragma unroll
    for (int c = 0; c < BR; c++) {
        int cnj = sCn[c];
        const float4* xr = (const float4*)(x + (size_t)cnj * TILE + (size_t)r * D);
        float4 x0 = xr[0], x1 = xr[1], x2 = xr[2], x3 = xr[3];
        float hh[16] = {x0.x,x0.y,x0.z,x0.w, x1.x,x1.y,x1.z,x1.w,
                        x2.x,x2.y,x2.z,x2.w, x3.x,x3.y,x3.z,x3.w};
        #pragma unroll
        for (int f = 0; f < 16; f++) hh[f] = fmaf(y[f], sScale[c][f], hh[f]);

        float o[16];
        fc16(hh, sW, sb, o);           // store fc(h) for next level

        float4* dst = (float4*)(ybuf + ((size_t)p * BR + c) * TILE + (size_t)r * D);
        dst[0] = make_float4(o[0],  o[1],  o[2],  o[3]);
        dst[1] = make_float4(o[4],  o[5],  o[6],  o[7]);
        dst[2] = make_float4(o[8],  o[9],  o[10], o[11]);
        dst[3] = make_float4(o[12], o[13], o[14], o[15]);
    }
}

// One half-tile per block over all NN nodes. out = x (cnt==0) or x + (sum leaf contribs)/cnt.
__global__ void __launch_bounds__(256) gather_kernel(
    const float* __restrict__ x, const float* __restrict__ A,
    const int* __restrict__ pe3, const int* __restrict__ pn3,
    float* __restrict__ out)
{
    __shared__ float sScale[CH][16];
    __shared__ int   sPe[CH];

    const int node = blockIdx.x >> 1;
    const int half = blockIdx.x & 1;
    const int t    = threadIdx.x;
    const int r    = half * HALF_ROWS + t;

    const int cnt = g_counts[node];
    const float4* xr = (const float4*)(x + (size_t)node * TILE + (size_t)r * D);
    float4 o0 = xr[0], o1 = xr[1], o2 = xr[2], o3 = xr[3];

    if (cnt > 0) {
        float acc[16];
        #pragma unroll
        for (int f = 0; f < 16; f++) acc[f] = 0.f;
        const int off = g_off[node];

        for (int base = 0; base < cnt; base += CH) {
            int m = min(CH, cnt - base);
            __syncthreads();
            if (t < m * 16) {
                int c = t >> 4, f = t & 15;
                int j = g_perm[off + base + c];
                sScale[c][f] = A[(size_t)f * NN * NN + (size_t)pn3[j] * NN + (size_t)node];
                if (f == 0) sPe[c] = pe3[j];
            }
            __syncthreads();
            for (int c = 0; c < m; c++) {
                const float4* yr = (const float4*)(g_y2 + (size_t)sPe[c] * TILE + (size_t)r * D);
                float4 y0 = yr[0], y1 = yr[1], y2 = yr[2], y3 = yr[3];
                acc[0]  = fmaf(y0.x, sScale[c][0],  acc[0]);
                acc[1]  = fmaf(y0.y, sScale[c][1],  acc[1]);
                acc[2]  = fmaf(y0.z, sScale[c][2],  acc[2]);
                acc[3]  = fmaf(y0.w, sScale[c][3],  acc[3]);
                acc[4]  = fmaf(y1.x, sScale[c][4],  acc[4]);
                acc[5]  = fmaf(y1.y, sScale[c][5],  acc[5]);
                acc[6]  = fmaf(y1.z, sScale[c][6],  acc[6]);
                acc[7]  = fmaf(y1.w, sScale[c][7],  acc[7]);
                acc[8]  = fmaf(y2.x, sScale[c][8],  acc[8]);
                acc[9]  = fmaf(y2.y, sScale[c][9],  acc[9]);
                acc[10] = fmaf(y2.z, sScale[c][10], acc[10]);
                acc[11] = fmaf(y2.w, sScale[c][11], acc[11]);
                acc[12] = fmaf(y3.x, sScale[c][12], acc[12]);
                acc[13] = fmaf(y3.y, sScale[c][13], acc[13]);
                acc[14] = fmaf(y3.z, sScale[c][14], acc[14]);
                acc[15] = fmaf(y3.w, sScale[c][15], acc[15]);
            }
        }
        const float inv = 1.0f / (float)cnt;
        o0.x += acc[0]*inv;  o0.y += acc[1]*inv;  o0.z += acc[2]*inv;  o0.w += acc[3]*inv;
        o1.x += acc[4]*inv;  o1.y += acc[5]*inv;  o1.z += acc[6]*inv;  o1.w += acc[7]*inv;
        o2.x += acc[8]*inv;  o2.y += acc[9]*inv;  o2.z += acc[10]*inv; o2.w += acc[11]*inv;
        o3.x += acc[12]*inv; o3.y += acc[13]*inv; o3.z += acc[14]*inv; o3.w += acc[15]*inv;
    }

    float4* dst = (float4*)(out + (size_t)node * TILE + (size_t)r * D);
    dst[0] = o0; dst[1] = o1; dst[2] = o2; dst[3] = o3;
}

extern "C" void kernel_launch(void* const* d_in, const int* in_sizes, int n_in,
                              void* d_out, int out_size) {
    const float* x    = (const float*)d_in[0];
    const float* A    = (const float*)d_in[1];
    const float* W    = (const float*)d_in[2];
    const float* b    = (const float*)d_in[3];
    const int*   root = (const int*)d_in[4];
    const int*   pe1  = (const int*)d_in[5];
    const int*   pn1  = (const int*)d_in[6];
    const int*   cn1  = (const int*)d_in[7];
    const int*   pe2  = (const int*)d_in[8];
    const int*   pn2  = (const int*)d_in[9];
    const int*   cn2  = (const int*)d_in[10];
    const int*   pe3  = (const int*)d_in[11];
    const int*   pn3  = (const int*)d_in[12];
    const int*   cn3  = (const int*)d_in[13];
    float* out = (float*)d_out;

    const int n1 = in_sizes[5];    // 600
    const int n2 = in_sizes[8];    // 1800
    const int n3 = in_sizes[11];   // 5400

    prep_kernel<<<1, 1024>>>(cn3, n3);
    level_kernel<0><<<2 * (n1 / BR), 256>>>(x, A, W, b, root, pe1, pn1, cn1);
    level_kernel<1><<<2 * (n2 / BR), 256>>>(x, A, W, b, root, pe2, pn2, cn2);
    gather_kernel<<<2 * NN, 256>>>(x, A, pe3, pn3, out);
}

// round 3
// speedup vs baseline: 1.3191x; 1.0655x over previous
#include <cuda_runtime.h>
#include <cstdint>

#define NN    2000
#define D     16
#define TILE  8192           // B*T*D = 8*64*16
#define BR    3
#define MAXLEAF 8192
#define CH    16             // leaf chunk in gather (covers max count in one shot)

// Scratch (device globals: no allocation allowed in kernel_launch)
__device__ float g_y1[600  * TILE];   // fc(h1)
__device__ float g_y2[1800 * TILE];   // fc(h2)
__device__ int   g_counts[NN];
__device__ int   g_off[NN];
__device__ int   g_perm[MAXLEAF];

__device__ __forceinline__ void fc16(const float h[16], const float* __restrict__ sW,
                                     const float* __restrict__ sb, float y[16]) {
    #pragma unroll
    for (int f = 0; f < 16; f++) y[f] = sb[f];
    #pragma unroll
    for (int d = 0; d < 16; d++) {
        float hd = h[d];
        #pragma unroll
        for (int f = 0; f < 16; f++) y[f] = fmaf(hd, sW[f*16 + d], y[f]);
    }
}

// One block: counts, exclusive-scan offsets, scatter permutation.
__global__ void __launch_bounds__(1024) prep_kernel(const int* __restrict__ cn3, int n3) {
    __shared__ int sCnt[2048];
    __shared__ int sScan[2048];
    const int t = threadIdx.x;

    sCnt[t] = 0; sCnt[t + 1024] = 0;
    __syncthreads();
    for (int j = t; j < n3; j += 1024) atomicAdd(&sCnt[cn3[j]], 1);
    __syncthreads();

    sScan[t]        = (t == 0) ? 0 : sCnt[t - 1];
    sScan[t + 1024] = sCnt[t + 1023];
    __syncthreads();
    for (int d = 1; d < 2048; d <<= 1) {
        int a = sScan[t]        + ((t >= d)        ? sScan[t - d]        : 0);
        int b = sScan[t + 1024] + ((t + 1024 >= d) ? sScan[t + 1024 - d] : 0);
        __syncthreads();
        sScan[t] = a; sScan[t + 1024] = b;
        __syncthreads();
    }

    if (t < NN)        { g_counts[t] = sCnt[t];           g_off[t] = sScan[t]; }
    if (t + 1024 < NN) { g_counts[t+1024] = sCnt[t+1024]; g_off[t+1024] = sScan[t+1024]; }

    sCnt[t] = 0; sCnt[t + 1024] = 0;
    __syncthreads();
    for (int j = t; j < n3; j += 1024) {
        int c = cn3[j];
        int pos = atomicAdd(&sCnt[c], 1);
        g_perm[sScan[c] + pos] = j;
    }
}

// Quarter-tile blocks: 128 threads, each owning one (b,t) row of 16 floats.
// MODE 0: parent = x[root_ids[pe]] (apply fc); store y1 = fc(h1)
// MODE 1: parent = g_y1[pe] (already fc'd);   store y2 = fc(h2)
template<int MODE>
__global__ void __launch_bounds__(128) level_kernel(
    const float* __restrict__ x, const float* __restrict__ A,
    const float* __restrict__ W, const float* __restrict__ bias,
    const int* __restrict__ root_ids,
    const int* __restrict__ pe, const int* __restrict__ pn, const int* __restrict__ cn)
{
    __shared__ float sW[256];
    __shared__ float sb[16];
    __shared__ float sScale[BR][16];
    __shared__ int   sCn[BR];

    const int p = blockIdx.x >> 2;
    const int q = blockIdx.x & 3;
    const int t = threadIdx.x;
    const int r = q * 128 + t;

    sW[t] = W[t];
    sW[t + 128] = W[t + 128];
    if (t < 16) sb[t] = bias[t];
    if (t < BR * 16) {
        int c = t >> 4, f = t & 15;
        int j = p * BR + c;
        int pnj = pn[j], cnj = cn[j];
        sScale[c][f] = A[(size_t)f * NN * NN + (size_t)pnj * NN + (size_t)cnj];
        if (f == 0) sCn[c] = cnj;
    }

    const float* ptile;
    {
        int pidx = pe[p * BR];
        if (MODE == 0) ptile = x    + (size_t)root_ids[pidx] * TILE;
        else           ptile = g_y1 + (size_t)pidx * TILE;
    }
    const float4* pr = (const float4*)(ptile + (size_t)r * D);
    float4 a0 = pr[0], a1 = pr[1], a2 = pr[2], a3 = pr[3];
    float h[16] = {a0.x,a0.y,a0.z,a0.w, a1.x,a1.y,a1.z,a1.w,
                   a2.x,a2.y,a2.z,a2.w, a3.x,a3.y,a3.z,a3.w};
    __syncthreads();

    float y[16];
    if (MODE == 0) {
        fc16(h, sW, sb, y);            // y = fc(parent)
    } else {
        #pragma unroll
        for (int f = 0; f < 16; f++) y[f] = h[f];   // parent already fc'd
    }

    float* ybuf = (MODE == 0) ? g_y1 : g_y2;
    #pragma unroll
    for (int c = 0; c < BR; c++) {
        int cnj = sCn[c];
        const float4* xr = (const float4*)(x + (size_t)cnj * TILE + (size_t)r * D);
        float4 x0 = xr[0], x1 = xr[1], x2 = xr[2], x3 = xr[3];
        float hh[16] = {x0.x,x0.y,x0.z,x0.w, x1.x,x1.y,x1.z,x1.w,
                        x2.x,x2.y,x2.z,x2.w, x3.x,x3.y,x3.z,x3.w};
        #pragma unroll
        for (int f = 0; f < 16; f++) hh[f] = fmaf(y[f], sScale[c][f], hh[f]);

        float o[16];
        fc16(hh, sW, sb, o);           // store fc(h) for next level

        float4* dst = (float4*)(ybuf + ((size_t)p * BR + c) * TILE + (size_t)r * D);
        dst[0] = make_float4(o[0],  o[1],  o[2],  o[3]);
        dst[1] = make_float4(o[4],  o[5],  o[6],  o[7]);
        dst[2] = make_float4(o[8],  o[9],  o[10], o[11]);
        dst[3] = make_float4(o[12], o[13], o[14], o[15]);
    }
}

// Quarter-tile blocks: 256 threads, 2 threads per row (each owns 8 contiguous floats).
// out = x (cnt==0) or x + (sum leaf contribs)/cnt.
__global__ void __launch_bounds__(256) gather_kernel(
    const float* __restrict__ x, const float* __restrict__ A,
    const int* __restrict__ pe3, const int* __restrict__ pn3,
    float* __restrict__ out)
{
    __shared__ float sScale[CH][16];
    __shared__ int   sPe[CH];

    const int node = blockIdx.x >> 2;
    const int q    = blockIdx.x & 3;
    const int t    = threadIdx.x;
    const int row  = q * 128 + (t >> 1);
    const int part = (t & 1) * 8;                  // float offset within row

    const int cnt = g_counts[node];
    const size_t eoff = (size_t)node * TILE + (size_t)row * D + part;
    const float4* xr = (const float4*)(x + eoff);
    float4 o0 = xr[0], o1 = xr[1];

    if (cnt > 0) {
        float acc[8];
        #pragma unroll
        for (int f = 0; f < 8; f++) acc[f] = 0.f;
        const int off = g_off[node];

        for (int base = 0; base < cnt; base += CH) {
            int m = min(CH, cnt - base);
            if (base) __syncthreads();
            if (t < m * 16) {
                int c = t >> 4, f = t & 15;
                int j = g_perm[off + base + c];
                sScale[c][f] = A[(size_t)f * NN * NN + (size_t)pn3[j] * NN + (size_t)node];
                if (f == 0) sPe[c] = pe3[j];
            }
            __syncthreads();
            for (int c = 0; c < m; c++) {
                const float4* yr = (const float4*)(g_y2 + (size_t)sPe[c] * TILE
                                                   + (size_t)row * D + part);
                float4 y0 = yr[0], y1 = yr[1];
                const float* sc = &sScale[c][part];
                acc[0] = fmaf(y0.x, sc[0], acc[0]);
                acc[1] = fmaf(y0.y, sc[1], acc[1]);
                acc[2] = fmaf(y0.z, sc[2], acc[2]);
                acc[3] = fmaf(y0.w, sc[3], acc[3]);
                acc[4] = fmaf(y1.x, sc[4], acc[4]);
                acc[5] = fmaf(y1.y, sc[5], acc[5]);
                acc[6] = fmaf(y1.z, sc[6], acc[6]);
                acc[7] = fmaf(y1.w, sc[7], acc[7]);
            }
        }
        const float inv = 1.0f / (float)cnt;
        o0.x += acc[0]*inv; o0.y += acc[1]*inv; o0.z += acc[2]*inv; o0.w += acc[3]*inv;
        o1.x += acc[4]*inv; o1.y += acc[5]*inv; o1.z += acc[6]*inv; o1.w += acc[7]*inv;
    }

    float4* dst = (float4*)(out + eoff);
    dst[0] = o0; dst[1] = o1;
}

extern "C" void kernel_launch(void* const* d_in, const int* in_sizes, int n_in,
                              void* d_out, int out_size) {
    const float* x    = (const float*)d_in[0];
    const float* A    = (const float*)d_in[1];
    const float* W    = (const float*)d_in[2];
    const float* b    = (const float*)d_in[3];
    const int*   root = (const int*)d_in[4];
    const int*   pe1  = (const int*)d_in[5];
    const int*   pn1  = (const int*)d_in[6];
    const int*   cn1  = (const int*)d_in[7];
    const int*   pe2  = (const int*)d_in[8];
    const int*   pn2  = (const int*)d_in[9];
    const int*   cn2  = (const int*)d_in[10];
    const int*   pe3  = (const int*)d_in[11];
    const int*   pn3  = (const int*)d_in[12];
    const int*   cn3  = (const int*)d_in[13];
    float* out = (float*)d_out;

    const int n1 = in_sizes[5];    // 600
    const int n2 = in_sizes[8];    // 1800
    const int n3 = in_sizes[11];   // 5400

    prep_kernel<<<1, 1024>>>(cn3, n3);
    level_kernel<0><<<4 * (n1 / BR), 128>>>(x, A, W, b, root, pe1, pn1, cn1);
    level_kernel<1><<<4 * (n2 / BR), 128>>>(x, A, W, b, root, pe2, pn2, cn2);
    gather_kernel<<<4 * NN, 256>>>(x, A, pe3, pn3, out);
}

// round 4
// speedup vs baseline: 1.6365x; 1.2406x over previous
#include <cuda_runtime.h>
#include <cstdint>

#define NN    2000
#define D     16
#define TILE  8192           // B*T*D = 8*64*16
#define BR    3
#define MAXLEAF 8192

// Scratch (device globals: no allocation allowed in kernel_launch)
__device__ float g_y2[1800 * TILE];   // fc(h2), consumed by gather
__device__ int   g_counts[NN];
__device__ int   g_off[NN];
__device__ int   g_perm[MAXLEAF];

// One block: counts, exclusive-scan offsets, scatter permutation.
__global__ void __launch_bounds__(1024) prep_kernel(const int* __restrict__ cn3, int n3) {
    __shared__ int sCnt[2048];
    __shared__ int sScan[2048];
    const int t = threadIdx.x;

    sCnt[t] = 0; sCnt[t + 1024] = 0;
    __syncthreads();
    for (int j = t; j < n3; j += 1024) atomicAdd(&sCnt[cn3[j]], 1);
    __syncthreads();

    sScan[t]        = (t == 0) ? 0 : sCnt[t - 1];
    sScan[t + 1024] = sCnt[t + 1023];
    __syncthreads();
    for (int d = 1; d < 2048; d <<= 1) {
        int a = sScan[t]        + ((t >= d)        ? sScan[t - d]        : 0);
        int b = sScan[t + 1024] + ((t + 1024 >= d) ? sScan[t + 1024 - d] : 0);
        __syncthreads();
        sScan[t] = a; sScan[t + 1024] = b;
        __syncthreads();
    }

    if (t < NN)        { g_counts[t] = sCnt[t];           g_off[t] = sScan[t]; }
    if (t + 1024 < NN) { g_counts[t+1024] = sCnt[t+1024]; g_off[t+1024] = sScan[t+1024]; }

    sCnt[t] = 0; sCnt[t + 1024] = 0;
    __syncthreads();
    for (int j = t; j < n3; j += 1024) {
        int c = cn3[j];
        int pos = atomicAdd(&sCnt[c], 1);
        g_perm[sScan[c] + pos] = j;
    }
}

// fc over 16 features with 2 threads/row: each thread owns 8 contiguous features
// (part = 0 or 8); partner half fetched via shfl_xor lane^1.
__device__ __forceinline__ void fc8(const float h[8], int part,
                                    const float* __restrict__ sW,
                                    const float* __restrict__ sb, float y[8]) {
    float ho[8];
    #pragma unroll
    for (int d = 0; d < 8; d++) ho[d] = __shfl_xor_sync(0xffffffffu, h[d], 1);
    const int op = part ^ 8;
    #pragma unroll
    for (int f = 0; f < 8; f++) {
        const float* wr = sW + (part + f) * 16;
        float acc = sb[part + f];
        #pragma unroll
        for (int d = 0; d < 8; d++) acc = fmaf(h[d],  wr[part + d], acc);
        #pragma unroll
        for (int d = 0; d < 8; d++) acc = fmaf(ho[d], wr[op + d],   acc);
        y[f] = acc;
    }
}

// Fused levels 0+1: one block per (root-parent, quarter-tile).
// Computes y2[j2] = fc(h2[j2]) for the 9 grandchildren of root rp, where
//   h1 = fc(x[root])*scale1 + x[cn1],  h2 = fc(h1)*scale2 + x[cn2].
// Relies on pe = repeat(arange, BR) structure (children of a parent are consecutive).
__global__ void __launch_bounds__(256) tree_kernel(
    const float* __restrict__ x, const float* __restrict__ A,
    const float* __restrict__ W, const float* __restrict__ bias,
    const int* __restrict__ root_ids,
    const int* __restrict__ pn1, const int* __restrict__ cn1,
    const int* __restrict__ pn2, const int* __restrict__ cn2)
{
    __shared__ float sW[256];
    __shared__ float sb16[16];
    __shared__ float sS1[3][16];
    __shared__ float sS2[9][16];
    __shared__ int   sCn1[3];
    __shared__ int   sCn2[9];

    const int rp = blockIdx.x >> 2;
    const int q  = blockIdx.x & 3;
    const int t  = threadIdx.x;

    sW[t] = W[t];
    if (t < 16) sb16[t] = bias[t];
    if (t < 48) {
        int c = t >> 4, f = t & 15;
        int j1 = rp * 3 + c;
        int pnj = pn1[j1], cnj = cn1[j1];
        sS1[c][f] = A[(size_t)f * NN * NN + (size_t)pnj * NN + (size_t)cnj];
        if (f == 0) sCn1[c] = cnj;
    } else if (t < 48 + 144) {
        int u = t - 48;
        int c = u >> 4, f = u & 15;
        int j2 = rp * 9 + c;
        int pnj = pn2[j2], cnj = cn2[j2];
        sS2[c][f] = A[(size_t)f * NN * NN + (size_t)pnj * NN + (size_t)cnj];
        if (f == 0) sCn2[c] = cnj;
    }

    const int row  = q * 128 + (t >> 1);
    const int part = (t & 1) * 8;
    const size_t roff = (size_t)row * D + part;

    float h[8];
    {
        const float4* pr = (const float4*)(x + (size_t)root_ids[rp] * TILE + roff);
        float4 a0 = pr[0], a1 = pr[1];
        h[0]=a0.x; h[1]=a0.y; h[2]=a0.z; h[3]=a0.w;
        h[4]=a1.x; h[5]=a1.y; h[6]=a1.z; h[7]=a1.w;
    }
    __syncthreads();

    float yp[8];
    fc8(h, part, sW, sb16, yp);          // fc(root)

    #pragma unroll
    for (int c1 = 0; c1 < 3; c1++) {
        float h1[8];
        {
            const float4* xr = (const float4*)(x + (size_t)sCn1[c1] * TILE + roff);
            float4 x0 = xr[0], x1 = xr[1];
            h1[0]=fmaf(yp[0],sS1[c1][part+0],x0.x);
            h1[1]=fmaf(yp[1],sS1[c1][part+1],x0.y);
            h1[2]=fmaf(yp[2],sS1[c1][part+2],x0.z);
            h1[3]=fmaf(yp[3],sS1[c1][part+3],x0.w);
            h1[4]=fmaf(yp[4],sS1[c1][part+4],x1.x);
            h1[5]=fmaf(yp[5],sS1[c1][part+5],x1.y);
            h1[6]=fmaf(yp[6],sS1[c1][part+6],x1.z);
            h1[7]=fmaf(yp[7],sS1[c1][part+7],x1.w);
        }
        float y1[8];
        fc8(h1, part, sW, sb16, y1);     // fc(h1) feeds level-2 children

        #pragma unroll
        for (int c2 = 0; c2 < 3; c2++) {
            const int cc = c1 * 3 + c2;
            float h2[8];
            {
                const float4* xr = (const float4*)(x + (size_t)sCn2[cc] * TILE + roff);
                float4 x0 = xr[0], x1 = xr[1];
                h2[0]=fmaf(y1[0],sS2[cc][part+0],x0.x);
                h2[1]=fmaf(y1[1],sS2[cc][part+1],x0.y);
                h2[2]=fmaf(y1[2],sS2[cc][part+2],x0.z);
                h2[3]=fmaf(y1[3],sS2[cc][part+3],x0.w);
                h2[4]=fmaf(y1[4],sS2[cc][part+4],x1.x);
                h2[5]=fmaf(y1[5],sS2[cc][part+5],x1.y);
                h2[6]=fmaf(y1[6],sS2[cc][part+6],x1.z);
                h2[7]=fmaf(y1[7],sS2[cc][part+7],x1.w);
            }
            float y2v[8];
            fc8(h2, part, sW, sb16, y2v); // store fc(h2) for gather

            float4* dst = (float4*)(g_y2 + ((size_t)rp * 9 + cc) * TILE + roff);
            dst[0] = make_float4(y2v[0], y2v[1], y2v[2], y2v[3]);
            dst[1] = make_float4(y2v[4], y2v[5], y2v[6], y2v[7]);
        }
    }
}

// Quarter-tile blocks, 2 threads/row. out = x (cnt==0) or x + (sum leaf contribs)/cnt.
// 4-wide leaf unroll with zero-padded scales for high per-thread MLP.
__global__ void __launch_bounds__(256) gather_kernel(
    const float* __restrict__ x, const float* __restrict__ A,
    const int* __restrict__ pe3, const int* __restrict__ pn3,
    float* __restrict__ out)
{
    __shared__ float sScale[16][16];
    __shared__ int   sPe[16];

    const int node = blockIdx.x >> 2;
    const int q    = blockIdx.x & 3;
    const int t    = threadIdx.x;
    const int row  = q * 128 + (t >> 1);
    const int part = (t & 1) * 8;

    const int cnt = g_counts[node];
    const size_t eoff = (size_t)node * TILE + (size_t)row * D + part;
    const float4* xr = (const float4*)(x + eoff);
    float4 o0 = xr[0], o1 = xr[1];

    if (cnt > 0) {
        float acc[8];
        #pragma unroll
        for (int f = 0; f < 8; f++) acc[f] = 0.f;
        const int off = g_off[node];
        const size_t roff = (size_t)row * D + part;

        for (int base = 0; base < cnt; base += 16) {
            const int m  = min(16, cnt - base);
            const int mp = (m + 3) & ~3;
            if (base) __syncthreads();
            {
                int c = t >> 4, f = t & 15;
                if (c < m) {
                    int j = g_perm[off + base + c];
                    sScale[c][f] = A[(size_t)f * NN * NN + (size_t)pn3[j] * NN + (size_t)node];
                    if (f == 0) sPe[c] = pe3[j];
                } else if (c < mp) {
                    sScale[c][f] = 0.f;                        // padded: zero contribution
                    if (f == 0) sPe[c] = pe3[g_perm[off + base]]; // valid duplicate address
                }
            }
            __syncthreads();

            for (int cb = 0; cb < mp; cb += 4) {
                const float4* p0 = (const float4*)(g_y2 + (size_t)sPe[cb+0] * TILE + roff);
                const float4* p1 = (const float4*)(g_y2 + (size_t)sPe[cb+1] * TILE + roff);
                const float4* p2 = (const float4*)(g_y2 + (size_t)sPe[cb+2] * TILE + roff);
                const float4* p3 = (const float4*)(g_y2 + (size_t)sPe[cb+3] * TILE + roff);
                float4 a0 = p0[0], a1 = p0[1];
                float4 b0 = p1[0], b1 = p1[1];
                float4 c0 = p2[0], c1 = p2[1];
                float4 d0 = p3[0], d1 = p3[1];
                const float* s0 = &sScale[cb+0][part];
                const float* s1 = &sScale[cb+1][part];
                const float* s2 = &sScale[cb+2][part];
                const float* s3 = &sScale[cb+3][part];
                acc[0]=fmaf(a0.x,s0[0],acc[0]); acc[1]=fmaf(a0.y,s0[1],acc[1]);
                acc[2]=fmaf(a0.z,s0[2],acc[2]); acc[3]=fmaf(a0.w,s0[3],acc[3]);
                acc[4]=fmaf(a1.x,s0[4],acc[4]); acc[5]=fmaf(a1.y,s0[5],acc[5]);
                acc[6]=fmaf(a1.z,s0[6],acc[6]); acc[7]=fmaf(a1.w,s0[7],acc[7]);
                acc[0]=fmaf(b0.x,s1[0],acc[0]); acc[1]=fmaf(b0.y,s1[1],acc[1]);
                acc[2]=fmaf(b0.z,s1[2],acc[2]); acc[3]=fmaf(b0.w,s1[3],acc[3]);
                acc[4]=fmaf(b1.x,s1[4],acc[4]); acc[5]=fmaf(b1.y,s1[5],acc[5]);
                acc[6]=fmaf(b1.z,s1[6],acc[6]); acc[7]=fmaf(b1.w,s1[7],acc[7]);
                acc[0]=fmaf(c0.x,s2[0],acc[0]); acc[1]=fmaf(c0.y,s2[1],acc[1]);
                acc[2]=fmaf(c0.z,s2[2],acc[2]); acc[3]=fmaf(c0.w,s2[3],acc[3]);
                acc[4]=fmaf(c1.x,s2[4],acc[4]); acc[5]=fmaf(c1.y,s2[5],acc[5]);
                acc[6]=fmaf(c1.z,s2[6],acc[6]); acc[7]=fmaf(c1.w,s2[7],acc[7]);
                acc[0]=fmaf(d0.x,s3[0],acc[0]); acc[1]=fmaf(d0.y,s3[1],acc[1]);
                acc[2]=fmaf(d0.z,s3[2],acc[2]); acc[3]=fmaf(d0.w,s3[3],acc[3]);
                acc[4]=fmaf(d1.x,s3[4],acc[4]); acc[5]=fmaf(d1.y,s3[5],acc[5]);
                acc[6]=fmaf(d1.z,s3[6],acc[6]); acc[7]=fmaf(d1.w,s3[7],acc[7]);
            }
        }
        const float inv = 1.0f / (float)cnt;
        o0.x += acc[0]*inv; o0.y += acc[1]*inv; o0.z += acc[2]*inv; o0.w += acc[3]*inv;
        o1.x += acc[4]*inv; o1.y += acc[5]*inv; o1.z += acc[6]*inv; o1.w += acc[7]*inv;
    }

    float4* dst = (float4*)(out + eoff);
    dst[0] = o0; dst[1] = o1;
}

extern "C" void kernel_launch(void* const* d_in, const int* in_sizes, int n_in,
                              void* d_out, int out_size) {
    const float* x    = (const float*)d_in[0];
    const float* A    = (const float*)d_in[1];
    const float* W    = (const float*)d_in[2];
    const float* b    = (const float*)d_in[3];
    const int*   root = (const int*)d_in[4];
    const int*   pn1  = (const int*)d_in[6];
    const int*   cn1  = (const int*)d_in[7];
    const int*   pn2  = (const int*)d_in[9];
    const int*   cn2  = (const int*)d_in[10];
    const int*   pe3  = (const int*)d_in[11];
    const int*   pn3  = (const int*)d_in[12];
    const int*   cn3  = (const int*)d_in[13];
    float* out = (float*)d_out;

    const int n1 = in_sizes[5];    // 600
    const int n3 = in_sizes[11];   // 5400
    const int n_roots = n1 / BR;   // 200

    static cudaStream_t s_side = nullptr;
    static cudaEvent_t  ev_fork = nullptr, ev_join = nullptr;
    if (!s_side) {
        cudaStreamCreateWithFlags(&s_side, cudaStreamNonBlocking);
        cudaEventCreateWithFlags(&ev_fork, cudaEventDisableTiming);
        cudaEventCreateWithFlags(&ev_join, cudaEventDisableTiming);
    }

    // prep only feeds gather; run it concurrently with tree_kernel.
    cudaEventRecord(ev_fork, 0);
    cudaStreamWaitEvent(s_side, ev_fork, 0);
    prep_kernel<<<1, 1024, 0, s_side>>>(cn3, n3);
    cudaEventRecord(ev_join, s_side);

    tree_kernel<<<4 * n_roots, 256>>>(x, A, W, b, root, pn1, cn1, pn2, cn2);

    cudaStreamWaitEvent(0, ev_join, 0);
    gather_kernel<<<4 * NN, 256>>>(x, A, pe3, pn3, out);
}

// round 5
// speedup vs baseline: 1.7666x; 1.0795x over previous
#include <cuda_runtime.h>
#include <cstdint>

#define NN    2000
#define D     16
#define TILE  8192           // B*T*D = 8*64*16
#define BR    3
#define MAXLEAF 8192

// Scratch (device globals: no allocation allowed in kernel_launch)
__device__ float g_y2[1800 * TILE];   // fc(h2), consumed by gather
__device__ int   g_counts[NN];
__device__ int   g_off[NN];
__device__ int   g_perm[MAXLEAF];
__device__ int   g_pe[MAXLEAF];          // pe3[perm[k]], dense
__device__ float g_scl[MAXLEAF * 16];    // A[f, pn3[perm[k]], cn3[perm[k]]], dense

// One block: counts, exclusive-scan offsets, scatter permutation.
__global__ void __launch_bounds__(1024) prep_kernel(const int* __restrict__ cn3, int n3) {
    __shared__ int sCnt[2048];
    __shared__ int sScan[2048];
    const int t = threadIdx.x;

    sCnt[t] = 0; sCnt[t + 1024] = 0;
    __syncthreads();
    for (int j = t; j < n3; j += 1024) atomicAdd(&sCnt[cn3[j]], 1);
    __syncthreads();

    sScan[t]        = (t == 0) ? 0 : sCnt[t - 1];
    sScan[t + 1024] = sCnt[t + 1023];
    __syncthreads();
    for (int d = 1; d < 2048; d <<= 1) {
        int a = sScan[t]        + ((t >= d)        ? sScan[t - d]        : 0);
        int b = sScan[t + 1024] + ((t + 1024 >= d) ? sScan[t + 1024 - d] : 0);
        __syncthreads();
        sScan[t] = a; sScan[t + 1024] = b;
        __syncthreads();
    }

    if (t < NN)        { g_counts[t] = sCnt[t];           g_off[t] = sScan[t]; }
    if (t + 1024 < NN) { g_counts[t+1024] = sCnt[t+1024]; g_off[t+1024] = sScan[t+1024]; }

    sCnt[t] = 0; sCnt[t + 1024] = 0;
    __syncthreads();
    for (int j = t; j < n3; j += 1024) {
        int c = cn3[j];
        int pos = atomicAdd(&sCnt[c], 1);
        g_perm[sScan[c] + pos] = j;
    }
}

// Grid-parallel: resolve all gather-side indirection into dense arrays.
__global__ void __launch_bounds__(256) scale_fill_kernel(
    const float* __restrict__ A, const int* __restrict__ pe3,
    const int* __restrict__ pn3, const int* __restrict__ cn3, int n3)
{
    int idx = blockIdx.x * blockDim.x + threadIdx.x;     // over n3*16
    if (idx >= n3 * 16) return;
    int k = idx >> 4, f = idx & 15;
    int j = g_perm[k];
    g_scl[idx] = A[(size_t)f * NN * NN + (size_t)pn3[j] * NN + (size_t)cn3[j]];
    if (f == 0) g_pe[k] = pe3[j];
}

// fc over 16 features with 2 threads/row: each thread owns 8 contiguous features
// (part = 0 or 8); partner half fetched via shfl_xor lane^1.
__device__ __forceinline__ void fc8(const float h[8], int part,
                                    const float* __restrict__ sW,
                                    const float* __restrict__ sb, float y[8]) {
    float ho[8];
    #pragma unroll
    for (int d = 0; d < 8; d++) ho[d] = __shfl_xor_sync(0xffffffffu, h[d], 1);
    const int op = part ^ 8;
    #pragma unroll
    for (int f = 0; f < 8; f++) {
        const float* wr = sW + (part + f) * 16;
        float acc = sb[part + f];
        #pragma unroll
        for (int d = 0; d < 8; d++) acc = fmaf(h[d],  wr[part + d], acc);
        #pragma unroll
        for (int d = 0; d < 8; d++) acc = fmaf(ho[d], wr[op + d],   acc);
        y[f] = acc;
    }
}

// Fused levels 0+1: one block per (root-parent, quarter-tile).
__global__ void __launch_bounds__(256) tree_kernel(
    const float* __restrict__ x, const float* __restrict__ A,
    const float* __restrict__ W, const float* __restrict__ bias,
    const int* __restrict__ root_ids,
    const int* __restrict__ pn1, const int* __restrict__ cn1,
    const int* __restrict__ pn2, const int* __restrict__ cn2)
{
    __shared__ float sW[256];
    __shared__ float sb16[16];
    __shared__ float sS1[3][16];
    __shared__ float sS2[9][16];
    __shared__ int   sCn1[3];
    __shared__ int   sCn2[9];

    const int rp = blockIdx.x >> 2;
    const int q  = blockIdx.x & 3;
    const int t  = threadIdx.x;

    sW[t] = W[t];
    if (t < 16) sb16[t] = bias[t];
    if (t < 48) {
        int c = t >> 4, f = t & 15;
        int j1 = rp * 3 + c;
        int pnj = pn1[j1], cnj = cn1[j1];
        sS1[c][f] = A[(size_t)f * NN * NN + (size_t)pnj * NN + (size_t)cnj];
        if (f == 0) sCn1[c] = cnj;
    } else if (t < 48 + 144) {
        int u = t - 48;
        int c = u >> 4, f = u & 15;
        int j2 = rp * 9 + c;
        int pnj = pn2[j2], cnj = cn2[j2];
        sS2[c][f] = A[(size_t)f * NN * NN + (size_t)pnj * NN + (size_t)cnj];
        if (f == 0) sCn2[c] = cnj;
    }

    const int row  = q * 128 + (t >> 1);
    const int part = (t & 1) * 8;
    const size_t roff = (size_t)row * D + part;

    float h[8];
    {
        const float4* pr = (const float4*)(x + (size_t)root_ids[rp] * TILE + roff);
        float4 a0 = pr[0], a1 = pr[1];
        h[0]=a0.x; h[1]=a0.y; h[2]=a0.z; h[3]=a0.w;
        h[4]=a1.x; h[5]=a1.y; h[6]=a1.z; h[7]=a1.w;
    }
    __syncthreads();

    float yp[8];
    fc8(h, part, sW, sb16, yp);          // fc(root)

    #pragma unroll
    for (int c1 = 0; c1 < 3; c1++) {
        float h1[8];
        {
            const float4* xr = (const float4*)(x + (size_t)sCn1[c1] * TILE + roff);
            float4 x0 = xr[0], x1 = xr[1];
            h1[0]=fmaf(yp[0],sS1[c1][part+0],x0.x);
            h1[1]=fmaf(yp[1],sS1[c1][part+1],x0.y);
            h1[2]=fmaf(yp[2],sS1[c1][part+2],x0.z);
            h1[3]=fmaf(yp[3],sS1[c1][part+3],x0.w);
            h1[4]=fmaf(yp[4],sS1[c1][part+4],x1.x);
            h1[5]=fmaf(yp[5],sS1[c1][part+5],x1.y);
            h1[6]=fmaf(yp[6],sS1[c1][part+6],x1.z);
            h1[7]=fmaf(yp[7],sS1[c1][part+7],x1.w);
        }
        float y1[8];
        fc8(h1, part, sW, sb16, y1);     // fc(h1) feeds level-2 children

        #pragma unroll
        for (int c2 = 0; c2 < 3; c2++) {
            const int cc = c1 * 3 + c2;
            float h2[8];
            {
                const float4* xr = (const float4*)(x + (size_t)sCn2[cc] * TILE + roff);
                float4 x0 = xr[0], x1 = xr[1];
                h2[0]=fmaf(y1[0],sS2[cc][part+0],x0.x);
                h2[1]=fmaf(y1[1],sS2[cc][part+1],x0.y);
                h2[2]=fmaf(y1[2],sS2[cc][part+2],x0.z);
                h2[3]=fmaf(y1[3],sS2[cc][part+3],x0.w);
                h2[4]=fmaf(y1[4],sS2[cc][part+4],x1.x);
                h2[5]=fmaf(y1[5],sS2[cc][part+5],x1.y);
                h2[6]=fmaf(y1[6],sS2[cc][part+6],x1.z);
                h2[7]=fmaf(y1[7],sS2[cc][part+7],x1.w);
            }
            float y2v[8];
            fc8(h2, part, sW, sb16, y2v); // store fc(h2) for gather

            float4* dst = (float4*)(g_y2 + ((size_t)rp * 9 + cc) * TILE + roff);
            dst[0] = make_float4(y2v[0], y2v[1], y2v[2], y2v[3]);
            dst[1] = make_float4(y2v[4], y2v[5], y2v[6], y2v[7]);
        }
    }
}

// Quarter-tile blocks, 2 threads/row. out = x (cnt==0) or x + (sum leaf contribs)/cnt.
// Dense prefetched scales (no pointer chase); streaming hints on single-use traffic.
__global__ void __launch_bounds__(256) gather_kernel(
    const float* __restrict__ x, float* __restrict__ out)
{
    __shared__ float sScale[16][16];
    __shared__ int   sPe[16];

    const int node = blockIdx.x >> 2;
    const int q    = blockIdx.x & 3;
    const int t    = threadIdx.x;
    const int row  = q * 128 + (t >> 1);
    const int part = (t & 1) * 8;

    const int cnt = g_counts[node];
    const size_t eoff = (size_t)node * TILE + (size_t)row * D + part;
    const float4* xr = (const float4*)(x + eoff);
    float4 o0 = __ldcs(xr);       // x tile: single use, evict-first
    float4 o1 = __ldcs(xr + 1);

    if (cnt > 0) {
        float acc[8];
        #pragma unroll
        for (int f = 0; f < 8; f++) acc[f] = 0.f;
        const int off = g_off[node];
        const size_t roff = (size_t)row * D + part;

        for (int base = 0; base < cnt; base += 16) {
            const int m  = min(16, cnt - base);
            const int mp = (m + 3) & ~3;
            if (base) __syncthreads();
            {
                int c = t >> 4, f = t & 15;
                if (c < m) {
                    sScale[c][f] = g_scl[(size_t)(off + base + c) * 16 + f];
                    if (f == 0) sPe[c] = g_pe[off + base + c];
                } else if (c < mp) {
                    sScale[c][f] = 0.f;              // padded: zero contribution
                    if (f == 0) sPe[c] = g_pe[off];  // valid duplicate address
                }
            }
            __syncthreads();

            for (int cb = 0; cb < mp; cb += 4) {
                const float4* p0 = (const float4*)(g_y2 + (size_t)sPe[cb+0] * TILE + roff);
                const float4* p1 = (const float4*)(g_y2 + (size_t)sPe[cb+1] * TILE + roff);
                const float4* p2 = (const float4*)(g_y2 + (size_t)sPe[cb+2] * TILE + roff);
                const float4* p3 = (const float4*)(g_y2 + (size_t)sPe[cb+3] * TILE + roff);
                float4 a0 = p0[0], a1 = p0[1];
                float4 b0 = p1[0], b1 = p1[1];
                float4 c0 = p2[0], c1 = p2[1];
                float4 d0 = p3[0], d1 = p3[1];
                const float* s0 = &sScale[cb+0][part];
                const float* s1 = &sScale[cb+1][part];
                const float* s2 = &sScale[cb+2][part];
                const float* s3 = &sScale[cb+3][part];
                acc[0]=fmaf(a0.x,s0[0],acc[0]); acc[1]=fmaf(a0.y,s0[1],acc[1]);
                acc[2]=fmaf(a0.z,s0[2],acc[2]); acc[3]=fmaf(a0.w,s0[3],acc[3]);
                acc[4]=fmaf(a1.x,s0[4],acc[4]); acc[5]=fmaf(a1.y,s0[5],acc[5]);
                acc[6]=fmaf(a1.z,s0[6],acc[6]); acc[7]=fmaf(a1.w,s0[7],acc[7]);
                acc[0]=fmaf(b0.x,s1[0],acc[0]); acc[1]=fmaf(b0.y,s1[1],acc[1]);
                acc[2]=fmaf(b0.z,s1[2],acc[2]); acc[3]=fmaf(b0.w,s1[3],acc[3]);
                acc[4]=fmaf(b1.x,s1[4],acc[4]); acc[5]=fmaf(b1.y,s1[5],acc[5]);
                acc[6]=fmaf(b1.z,s1[6],acc[6]); acc[7]=fmaf(b1.w,s1[7],acc[7]);
                acc[0]=fmaf(c0.x,s2[0],acc[0]); acc[1]=fmaf(c0.y,s2[1],acc[1]);
                acc[2]=fmaf(c0.z,s2[2],acc[2]); acc[3]=fmaf(c0.w,s2[3],acc[3]);
                acc[4]=fmaf(c1.x,s2[4],acc[4]); acc[5]=fmaf(c1.y,s2[5],acc[5]);
                acc[6]=fmaf(c1.z,s2[6],acc[6]); acc[7]=fmaf(c1.w,s2[7],acc[7]);
                acc[0]=fmaf(d0.x,s3[0],acc[0]); acc[1]=fmaf(d0.y,s3[1],acc[1]);
                acc[2]=fmaf(d0.z,s3[2],acc[2]); acc[3]=fmaf(d0.w,s3[3],acc[3]);
                acc[4]=fmaf(d1.x,s3[4],acc[4]); acc[5]=fmaf(d1.y,s3[5],acc[5]);
                acc[6]=fmaf(d1.z,s3[6],acc[6]); acc[7]=fmaf(d1.w,s3[7],acc[7]);
            }
        }
        const float inv = 1.0f / (float)cnt;
        o0.x += acc[0]*inv; o0.y += acc[1]*inv; o0.z += acc[2]*inv; o0.w += acc[3]*inv;
        o1.x += acc[4]*inv; o1.y += acc[5]*inv; o1.z += acc[6]*inv; o1.w += acc[7]*inv;
    }

    float4* dst = (float4*)(out + eoff);
    __stcs(dst,     o0);          // out: never re-read, evict-first
    __stcs(dst + 1, o1);
}

extern "C" void kernel_launch(void* const* d_in, const int* in_sizes, int n_in,
                              void* d_out, int out_size) {
    const float* x    = (const float*)d_in[0];
    const float* A    = (const float*)d_in[1];
    const float* W    = (const float*)d_in[2];
    const float* b    = (const float*)d_in[3];
    const int*   root = (const int*)d_in[4];
    const int*   pn1  = (const int*)d_in[6];
    const int*   cn1  = (const int*)d_in[7];
    const int*   pn2  = (const int*)d_in[9];
    const int*   cn2  = (const int*)d_in[10];
    const int*   pe3  = (const int*)d_in[11];
    const int*   pn3  = (const int*)d_in[12];
    const int*   cn3  = (const int*)d_in[13];
    float* out = (float*)d_out;

    const int n1 = in_sizes[5];    // 600
    const int n3 = in_sizes[11];   // 5400
    const int n_roots = n1 / BR;   // 200

    static cudaStream_t s_side = nullptr;
    static cudaEvent_t  ev_fork = nullptr, ev_join = nullptr;
    if (!s_side) {
        cudaStreamCreateWithFlags(&s_side, cudaStreamNonBlocking);
        cudaEventCreateWithFlags(&ev_fork, cudaEventDisableTiming);
        cudaEventCreateWithFlags(&ev_join, cudaEventDisableTiming);
    }

    // prep + scale resolve only feed gather; run them concurrently with tree_kernel.
    cudaEventRecord(ev_fork, 0);
    cudaStreamWaitEvent(s_side, ev_fork, 0);
    prep_kernel<<<1, 1024, 0, s_side>>>(cn3, n3);
    scale_fill_kernel<<<(n3 * 16 + 255) / 256, 256, 0, s_side>>>(A, pe3, pn3, cn3, n3);
    cudaEventRecord(ev_join, s_side);

    tree_kernel<<<4 * n_roots, 256>>>(x, A, W, b, root, pn1, cn1, pn2, cn2);

    cudaStreamWaitEvent(0, ev_join, 0);
    gather_kernel<<<4 * NN, 256>>>(x, out);
}

// round 6
// speedup vs baseline: 1.8293x; 1.0355x over previous
#include <cuda_runtime.h>
#include <cstdint>

#define NN    2000
#define D     16
#define TILE  8192           // B*T*D = 8*64*16
#define BR    3
#define MAXPAD 16384         // >= n3 + 3*NN

// Scratch (device globals: no allocation allowed in kernel_launch)
__device__ float g_y2[1800 * TILE];   // fc(h2), consumed by gather
__device__ int   g_counts[NN];
__device__ int   g_off[NN];           // padded exclusive offsets (multiples of 4)
__device__ int   g_perm[MAXPAD];      // leaf index, ~first for pad slots
__device__ int   g_pad_total;
__device__ __align__(16) int   g_pe[MAXPAD];        // pe3[perm[k]], dense
__device__ __align__(16) float g_scl[MAXPAD * 16];  // scales (0 for pad), dense

// One block: counts, padded exclusive-scan offsets, scatter permutation, pad fill.
__global__ void __launch_bounds__(1024) prep_kernel(const int* __restrict__ cn3, int n3) {
    __shared__ int sCnt[2048];
    __shared__ int sScan[2048];
    const int t = threadIdx.x;

    sCnt[t] = 0; sCnt[t + 1024] = 0;
    __syncthreads();
    for (int j = t; j < n3; j += 1024) atomicAdd(&sCnt[cn3[j]], 1);
    __syncthreads();

    // exclusive scan of PADDED counts (pad each to multiple of 4)
    sScan[t]        = (t == 0) ? 0 : ((sCnt[t - 1] + 3) & ~3);
    sScan[t + 1024] = (sCnt[t + 1023] + 3) & ~3;
    __syncthreads();
    for (int d = 1; d < 2048; d <<= 1) {
        int a = sScan[t]        + ((t >= d)        ? sScan[t - d]        : 0);
        int b = sScan[t + 1024] + ((t + 1024 >= d) ? sScan[t + 1024 - d] : 0);
        __syncthreads();
        sScan[t] = a; sScan[t + 1024] = b;
        __syncthreads();
    }

    if (t < NN)        { g_counts[t] = sCnt[t];           g_off[t] = sScan[t]; }
    if (t + 1024 < NN) { g_counts[t+1024] = sCnt[t+1024]; g_off[t+1024] = sScan[t+1024]; }
    if (t == 0) g_pad_total = sScan[NN - 1] + ((sCnt[NN - 1] + 3) & ~3);

    sCnt[t] = 0; sCnt[t + 1024] = 0;
    __syncthreads();
    for (int j = t; j < n3; j += 1024) {
        int c = cn3[j];
        int pos = atomicAdd(&sCnt[c], 1);
        g_perm[sScan[c] + pos] = j;
    }
    __syncthreads();

    // pad fill: duplicate first leaf index, flagged with ~ (scale will be 0)
    for (int i = t; i < NN; i += 1024) {
        int c = g_counts[i];
        if (c == 0) continue;
        int off = g_off[i];
        int pc = (c + 3) & ~3;
        int first = g_perm[off];
        for (int k = c; k < pc; k++) g_perm[off + k] = ~first;
    }
}

// Grid-parallel: resolve all gather-side indirection into dense arrays.
__global__ void __launch_bounds__(256) scale_fill_kernel(
    const float* __restrict__ A, const int* __restrict__ pe3,
    const int* __restrict__ pn3, const int* __restrict__ cn3)
{
    int idx = blockIdx.x * blockDim.x + threadIdx.x;     // over pad_total*16
    if (idx >= g_pad_total * 16) return;
    int k = idx >> 4, f = idx & 15;
    int j = g_perm[k];
    bool pad = (j < 0);
    if (pad) j = ~j;
    g_scl[idx] = pad ? 0.f
                     : A[(size_t)f * NN * NN + (size_t)pn3[j] * NN + (size_t)cn3[j]];
    if (f == 0) g_pe[k] = pe3[j];
}

// fc over 16 features with 2 threads/row: each thread owns 8 contiguous features
// (part = 0 or 8); partner half fetched via shfl_xor lane^1.
__device__ __forceinline__ void fc8(const float h[8], int part,
                                    const float* __restrict__ sW,
                                    const float* __restrict__ sb, float y[8]) {
    float ho[8];
    #pragma unroll
    for (int d = 0; d < 8; d++) ho[d] = __shfl_xor_sync(0xffffffffu, h[d], 1);
    const int op = part ^ 8;
    #pragma unroll
    for (int f = 0; f < 8; f++) {
        const float* wr = sW + (part + f) * 16;
        float acc = sb[part + f];
        #pragma unroll
        for (int d = 0; d < 8; d++) acc = fmaf(h[d],  wr[part + d], acc);
        #pragma unroll
        for (int d = 0; d < 8; d++) acc = fmaf(ho[d], wr[op + d],   acc);
        y[f] = acc;
    }
}

// Fused levels 0+1: one block per (root, eighth-tile). 128 threads, 2/row.
__global__ void __launch_bounds__(128) tree_kernel(
    const float* __restrict__ x, const float* __restrict__ A,
    const float* __restrict__ W, const float* __restrict__ bias,
    const int* __restrict__ root_ids,
    const int* __restrict__ pn1, const int* __restrict__ cn1,
    const int* __restrict__ pn2, const int* __restrict__ cn2)
{
    __shared__ float sW[256];
    __shared__ float sb16[16];
    __shared__ float sS1[3][16];
    __shared__ float sS2[9][16];
    __shared__ int   sCn1[3];
    __shared__ int   sCn2[9];

    const int rp  = blockIdx.x >> 3;
    const int oct = blockIdx.x & 7;
    const int t   = threadIdx.x;

    sW[t] = W[t];
    sW[t + 128] = W[t + 128];
    if (t < 16) sb16[t] = bias[t];

    // 192 scale entries loaded by 128 threads (two passes)
    #pragma unroll
    for (int pass = 0; pass < 2; pass++) {
        int u = t + pass * 128;
        if (u < 48) {
            int c = u >> 4, f = u & 15;
            int j1 = rp * 3 + c;
            int pnj = pn1[j1], cnj = cn1[j1];
            sS1[c][f] = A[(size_t)f * NN * NN + (size_t)pnj * NN + (size_t)cnj];
            if (f == 0) sCn1[c] = cnj;
        } else if (u < 192) {
            int v = u - 48;
            int c = v >> 4, f = v & 15;
            int j2 = rp * 9 + c;
            int pnj = pn2[j2], cnj = cn2[j2];
            sS2[c][f] = A[(size_t)f * NN * NN + (size_t)pnj * NN + (size_t)cnj];
            if (f == 0) sCn2[c] = cnj;
        }
    }

    const int row  = oct * 64 + (t >> 1);
    const int part = (t & 1) * 8;
    const size_t roff = (size_t)row * D + part;

    float h[8];
    {
        const float4* pr = (const float4*)(x + (size_t)root_ids[rp] * TILE + roff);
        float4 a0 = pr[0], a1 = pr[1];
        h[0]=a0.x; h[1]=a0.y; h[2]=a0.z; h[3]=a0.w;
        h[4]=a1.x; h[5]=a1.y; h[6]=a1.z; h[7]=a1.w;
    }
    __syncthreads();

    float yp[8];
    fc8(h, part, sW, sb16, yp);          // fc(root)

    #pragma unroll
    for (int c1 = 0; c1 < 3; c1++) {
        float h1[8];
        {
            const float4* xr = (const float4*)(x + (size_t)sCn1[c1] * TILE + roff);
            float4 x0 = xr[0], x1 = xr[1];
            h1[0]=fmaf(yp[0],sS1[c1][part+0],x0.x);
            h1[1]=fmaf(yp[1],sS1[c1][part+1],x0.y);
            h1[2]=fmaf(yp[2],sS1[c1][part+2],x0.z);
            h1[3]=fmaf(yp[3],sS1[c1][part+3],x0.w);
            h1[4]=fmaf(yp[4],sS1[c1][part+4],x1.x);
            h1[5]=fmaf(yp[5],sS1[c1][part+5],x1.y);
            h1[6]=fmaf(yp[6],sS1[c1][part+6],x1.z);
            h1[7]=fmaf(yp[7],sS1[c1][part+7],x1.w);
        }
        float y1[8];
        fc8(h1, part, sW, sb16, y1);     // fc(h1) feeds level-2 children

        #pragma unroll
        for (int c2 = 0; c2 < 3; c2++) {
            const int cc = c1 * 3 + c2;
            float h2[8];
            {
                const float4* xr = (const float4*)(x + (size_t)sCn2[cc] * TILE + roff);
                float4 x0 = xr[0], x1 = xr[1];
                h2[0]=fmaf(y1[0],sS2[cc][part+0],x0.x);
                h2[1]=fmaf(y1[1],sS2[cc][part+1],x0.y);
                h2[2]=fmaf(y1[2],sS2[cc][part+2],x0.z);
                h2[3]=fmaf(y1[3],sS2[cc][part+3],x0.w);
                h2[4]=fmaf(y1[4],sS2[cc][part+4],x1.x);
                h2[5]=fmaf(y1[5],sS2[cc][part+5],x1.y);
                h2[6]=fmaf(y1[6],sS2[cc][part+6],x1.z);
                h2[7]=fmaf(y1[7],sS2[cc][part+7],x1.w);
            }
            float y2v[8];
            fc8(h2, part, sW, sb16, y2v); // store fc(h2) for gather

            float4* dst = (float4*)(g_y2 + ((size_t)rp * 9 + cc) * TILE + roff);
            dst[0] = make_float4(y2v[0], y2v[1], y2v[2], y2v[3]);
            dst[1] = make_float4(y2v[4], y2v[5], y2v[6], y2v[7]);
        }
    }
}

// Eighth-tile blocks, 128 threads, 2/row. NO shared memory, NO syncthreads:
// padded 4-wide leaf loop; scales/pe are dense, L1-broadcast loads.
__global__ void __launch_bounds__(128) gather_kernel(
    const float* __restrict__ x, float* __restrict__ out)
{
    const int node = blockIdx.x >> 3;
    const int oct  = blockIdx.x & 7;
    const int t    = threadIdx.x;
    const int row  = oct * 64 + (t >> 1);
    const int part = (t & 1) * 8;

    const int cnt = g_counts[node];
    const size_t eoff = (size_t)node * TILE + (size_t)row * D + part;
    const float4* xr = (const float4*)(x + eoff);
    float4 o0 = __ldcs(xr);       // x tile: single use, evict-first
    float4 o1 = __ldcs(xr + 1);

    if (cnt > 0) {
        float acc[8];
        #pragma unroll
        for (int f = 0; f < 8; f++) acc[f] = 0.f;
        const int off = g_off[node];          // multiple of 4
        const int pc  = (cnt + 3) & ~3;
        const size_t roff = (size_t)row * D + part;

        for (int k = 0; k < pc; k += 4) {
            const int4 pe4 = *(const int4*)(g_pe + off + k);
            const float4* p0 = (const float4*)(g_y2 + (size_t)pe4.x * TILE + roff);
            const float4* p1 = (const float4*)(g_y2 + (size_t)pe4.y * TILE + roff);
            const float4* p2 = (const float4*)(g_y2 + (size_t)pe4.z * TILE + roff);
            const float4* p3 = (const float4*)(g_y2 + (size_t)pe4.w * TILE + roff);
            float4 a0 = p0[0], a1 = p0[1];
            float4 b0 = p1[0], b1 = p1[1];
            float4 c0 = p2[0], c1 = p2[1];
            float4 d0 = p3[0], d1 = p3[1];

            const float4* sp = (const float4*)(g_scl + (size_t)(off + k) * 16 + part);
            // leaf i scales at sp + i*4 (16 floats per leaf = 4 float4)
            float4 s0a = sp[0], s0b = sp[1];
            float4 s1a = sp[4], s1b = sp[5];
            float4 s2a = sp[8], s2b = sp[9];
            float4 s3a = sp[12], s3b = sp[13];

            acc[0]=fmaf(a0.x,s0a.x,acc[0]); acc[1]=fmaf(a0.y,s0a.y,acc[1]);
            acc[2]=fmaf(a0.z,s0a.z,acc[2]); acc[3]=fmaf(a0.w,s0a.w,acc[3]);
            acc[4]=fmaf(a1.x,s0b.x,acc[4]); acc[5]=fmaf(a1.y,s0b.y,acc[5]);
            acc[6]=fmaf(a1.z,s0b.z,acc[6]); acc[7]=fmaf(a1.w,s0b.w,acc[7]);

            acc[0]=fmaf(b0.x,s1a.x,acc[0]); acc[1]=fmaf(b0.y,s1a.y,acc[1]);
            acc[2]=fmaf(b0.z,s1a.z,acc[2]); acc[3]=fmaf(b0.w,s1a.w,acc[3]);
            acc[4]=fmaf(b1.x,s1b.x,acc[4]); acc[5]=fmaf(b1.y,s1b.y,acc[5]);
            acc[6]=fmaf(b1.z,s1b.z,acc[6]); acc[7]=fmaf(b1.w,s1b.w,acc[7]);

            acc[0]=fmaf(c0.x,s2a.x,acc[0]); acc[1]=fmaf(c0.y,s2a.y,acc[1]);
            acc[2]=fmaf(c0.z,s2a.z,acc[2]); acc[3]=fmaf(c0.w,s2a.w,acc[3]);
            acc[4]=fmaf(c1.x,s2b.x,acc[4]); acc[5]=fmaf(c1.y,s2b.y,acc[5]);
            acc[6]=fmaf(c1.z,s2b.z,acc[6]); acc[7]=fmaf(c1.w,s2b.w,acc[7]);

            acc[0]=fmaf(d0.x,s3a.x,acc[0]); acc[1]=fmaf(d0.y,s3a.y,acc[1]);
            acc[2]=fmaf(d0.z,s3a.z,acc[2]); acc[3]=fmaf(d0.w,s3a.w,acc[3]);
            acc[4]=fmaf(d1.x,s3b.x,acc[4]); acc[5]=fmaf(d1.y,s3b.y,acc[5]);
            acc[6]=fmaf(d1.z,s3b.z,acc[6]); acc[7]=fmaf(d1.w,s3b.w,acc[7]);
        }
        const float inv = 1.0f / (float)cnt;
        o0.x += acc[0]*inv; o0.y += acc[1]*inv; o0.z += acc[2]*inv; o0.w += acc[3]*inv;
        o1.x += acc[4]*inv; o1.y += acc[5]*inv; o1.z += acc[6]*inv; o1.w += acc[7]*inv;
    }

    float4* dst = (float4*)(out + eoff);
    __stcs(dst,     o0);          // out: never re-read, evict-first
    __stcs(dst + 1, o1);
}

extern "C" void kernel_launch(void* const* d_in, const int* in_sizes, int n_in,
                              void* d_out, int out_size) {
    const float* x    = (const float*)d_in[0];
    const float* A    = (const float*)d_in[1];
    const float* W    = (const float*)d_in[2];
    const float* b    = (const float*)d_in[3];
    const int*   root = (const int*)d_in[4];
    const int*   pn1  = (const int*)d_in[6];
    const int*   cn1  = (const int*)d_in[7];
    const int*   pn2  = (const int*)d_in[9];
    const int*   cn2  = (const int*)d_in[10];
    const int*   pe3  = (const int*)d_in[11];
    const int*   pn3  = (const int*)d_in[12];
    const int*   cn3  = (const int*)d_in[13];
    float* out = (float*)d_out;

    const int n1 = in_sizes[5];    // 600
    const int n3 = in_sizes[11];   // 5400
    const int n_roots = n1 / BR;   // 200

    static cudaStream_t s_side = nullptr;
    static cudaEvent_t  ev_fork = nullptr, ev_join = nullptr;
    if (!s_side) {
        cudaStreamCreateWithFlags(&s_side, cudaStreamNonBlocking);
        cudaEventCreateWithFlags(&ev_fork, cudaEventDisableTiming);
        cudaEventCreateWithFlags(&ev_join, cudaEventDisableTiming);
    }

    // prep + scale resolve only feed gather; run them concurrently with tree_kernel.
    cudaEventRecord(ev_fork, 0);
    cudaStreamWaitEvent(s_side, ev_fork, 0);
    prep_kernel<<<1, 1024, 0, s_side>>>(cn3, n3);
    const int padmax = n3 + 3 * NN;
    scale_fill_kernel<<<(padmax * 16 + 255) / 256, 256, 0, s_side>>>(A, pe3, pn3, cn3);
    cudaEventRecord(ev_join, s_side);

    tree_kernel<<<8 * n_roots, 128>>>(x, A, W, b, root, pn1, cn1, pn2, cn2);

    cudaStreamWaitEvent(0, ev_join, 0);
    gather_kernel<<<8 * NN, 128>>>(x, out);
}